// round 1
// baseline (speedup 1.0000x reference)
#include <cuda_runtime.h>
#include <cstdint>

// Problem constants (validated against runtime sizes where cheap).
#define D_IN   64
#define C_OUT  64
#define W_COLS 192        // C_OUT * 3 irreps
#define SH_DIM 9
#define TILE_E 32         // edges per block (8 warps x 4 edges)
#define R_E    4          // edges per warp
#define THREADS 256

// smem layout (floats):
//  [0, 12288)            W staged           (48 KB)
//  [12288, 12288+4096)   inv duplicated f32x2: 32 edges x 64 k x {v,v}  (16 KB)
//  [16384, 16384+4608)   stage: 8 warps x 576 floats                    (18 KB)
#define SM_W    0
#define SM_INV  12288
#define SM_STG  (12288 + 4096)
#define SMEM_FLOATS (12288 + 4096 + 8*576)

__device__ __forceinline__ void ffma2(unsigned long long& d,
                                      unsigned long long a,
                                      unsigned long long b) {
    asm("fma.rn.f32x2 %0, %1, %2, %0;" : "+l"(d) : "l"(a), "l"(b));
}

__global__ __launch_bounds__(THREADS, 2)
void sh_embed_kernel(const float* __restrict__ edge_vec,
                     const float* __restrict__ edge_inv,
                     const float* __restrict__ W_lin,
                     float* __restrict__ out,
                     int E) {
    extern __shared__ float smem[];
    float* Wsh = smem + SM_W;
    unsigned long long* inv2 = (unsigned long long*)(smem + SM_INV);
    float* stgAll = smem + SM_STG;

    const int tid  = threadIdx.x;
    const int wrp  = tid >> 5;
    const int cp   = tid & 31;          // channel pair id: channels 2cp, 2cp+1
    const int ebase = blockIdx.x * TILE_E;

    // ---- stage W [64][192] into smem (float4 coalesced) ----
    {
        const float4* src = (const float4*)W_lin;
        float4* dst = (float4*)Wsh;
        #pragma unroll
        for (int i = 0; i < 12; i++) {
            int idx = tid + i * THREADS;          // 12288/4 = 3072 float4
            dst[idx] = src[idx];
        }
    }

    // ---- stage invariants duplicated {v,v} : 32 rows x 64 cols ----
    {
        float2* inv2f = (float2*)inv2;   // [32][64] of float2
        #pragma unroll
        for (int i = 0; i < 2; i++) {
            int idx = tid + i * THREADS;          // 512 float4 loads total
            int row = idx >> 4;                   // 16 float4 per row
            int c4  = idx & 15;
            int e   = ebase + row;
            float4 v = make_float4(0.f, 0.f, 0.f, 0.f);
            if (e < E) v = ((const float4*)edge_inv)[(size_t)e * 16 + c4];
            float4* p = (float4*)&inv2f[row * 64 + 4 * c4];
            p[0] = make_float4(v.x, v.x, v.y, v.y);
            p[1] = make_float4(v.z, v.z, v.w, v.w);
        }
    }
    __syncthreads();

    // ---- mainloop: per-warp 4 edges, per-thread 2 channels via f32x2 ----
    unsigned long long acc[R_E][3];
    #pragma unroll
    for (int r = 0; r < R_E; r++) {
        acc[r][0] = 0ull; acc[r][1] = 0ull; acc[r][2] = 0ull;
    }

    const unsigned long long* Ip = inv2 + (size_t)(wrp * R_E) * 64;
    const float* Wp = Wsh + 6 * cp;

    #pragma unroll 8
    for (int k = 0; k < 64; k++) {
        const float* wk = Wp + k * W_COLS;
        unsigned long long b0 = *(const unsigned long long*)(wk);
        unsigned long long b1 = *(const unsigned long long*)(wk + 2);
        unsigned long long b2 = *(const unsigned long long*)(wk + 4);
        #pragma unroll
        for (int r = 0; r < R_E; r++) {
            unsigned long long iv = Ip[r * 64 + k];
            ffma2(acc[r][0], iv, b0);
            ffma2(acc[r][1], iv, b1);
            ffma2(acc[r][2], iv, b2);
        }
    }

    // ---- epilogue: SH weighting + coalesced store via smem staging ----
    const float SQ3   = 1.7320508075688772f;
    const float SQ5   = 2.2360679774997896f;
    const float SQ15  = 3.8729833462074170f;
    const float SQ15H = 1.9364916731037085f;

    float* stg = stgAll + wrp * 576;

    #pragma unroll
    for (int r = 0; r < R_E; r++) {
        int e = ebase + wrp * R_E + r;
        if (e >= E) break;   // uniform across warp

        // spherical harmonics (computed redundantly per lane; cheap)
        const float* ev = edge_vec + (size_t)e * 3;
        float vx = ev[0], vy = ev[1], vz = ev[2];
        float rn = rsqrtf(vx * vx + vy * vy + vz * vz);
        float x = vx * rn, y = vy * rn, z = vz * rn;
        float sh1 = SQ3 * x, sh2 = SQ3 * y, sh3 = SQ3 * z;
        float sh4 = SQ15 * x * z;
        float sh5 = SQ15 * x * y;
        float sh6 = SQ5 * (y * y - 0.5f * (x * x + z * z));
        float sh7 = SQ15 * y * z;
        float sh8 = SQ15H * (z * z - x * x);

        // unpack accumulators: acc[r][j] lo/hi = gemm cols 6cp+2j, 6cp+2j+1
        float w00 = __uint_as_float((unsigned)(acc[r][0] & 0xffffffffull));
        float w01 = __uint_as_float((unsigned)(acc[r][0] >> 32));
        float w02 = __uint_as_float((unsigned)(acc[r][1] & 0xffffffffull));
        float w10 = __uint_as_float((unsigned)(acc[r][1] >> 32));
        float w11 = __uint_as_float((unsigned)(acc[r][2] & 0xffffffffull));
        float w12 = __uint_as_float((unsigned)(acc[r][2] >> 32));

        float val[18];
        val[0] = w00;
        val[1] = w01 * sh1;  val[2] = w01 * sh2;  val[3] = w01 * sh3;
        val[4] = w02 * sh4;  val[5] = w02 * sh5;  val[6] = w02 * sh6;
        val[7] = w02 * sh7;  val[8] = w02 * sh8;
        val[9] = w10;
        val[10] = w11 * sh1; val[11] = w11 * sh2; val[12] = w11 * sh3;
        val[13] = w12 * sh4; val[14] = w12 * sh5; val[15] = w12 * sh6;
        val[16] = w12 * sh7; val[17] = w12 * sh8;

        float2* stg2 = (float2*)(stg) + 9 * cp;
        #pragma unroll
        for (int j = 0; j < 9; j++)
            stg2[j] = make_float2(val[2 * j], val[2 * j + 1]);

        __syncwarp();

        // coalesced copy: 576 floats = 4 x (32 lanes x float4) + 1 x (32 x float2)
        float* dst = out + (size_t)e * 576;
        #pragma unroll
        for (int j = 0; j < 4; j++) {
            int idx = j * 128 + cp * 4;
            float4 v = *(const float4*)&stg[idx];
            *(float4*)&dst[idx] = v;
        }
        {
            int idx = 512 + cp * 2;
            float2 v = *(const float2*)&stg[idx];
            *(float2*)&dst[idx] = v;
        }
        __syncwarp();
    }
}

extern "C" void kernel_launch(void* const* d_in, const int* in_sizes, int n_in,
                              void* d_out, int out_size) {
    const float* edge_vec = (const float*)d_in[0];  // [E,3]
    const float* edge_inv = (const float*)d_in[1];  // [E,64]
    const float* W_lin    = (const float*)d_in[2];  // [64,192]
    float* out = (float*)d_out;                     // [E,64,9]

    int E = in_sizes[0] / 3;
    int blocks = (E + TILE_E - 1) / TILE_E;
    size_t smem = SMEM_FLOATS * sizeof(float);

    static bool attr_set = false;
    if (!attr_set) {
        cudaFuncSetAttribute(sh_embed_kernel,
                             cudaFuncAttributeMaxDynamicSharedMemorySize,
                             (int)smem);
        attr_set = true;
    }
    sh_embed_kernel<<<blocks, THREADS, smem>>>(edge_vec, edge_inv, W_lin, out, E);
}

// round 4
// speedup vs baseline: 1.2271x; 1.2271x over previous
#include <cuda_runtime.h>
#include <cstdint>

#define D_IN   64
#define C_OUT  64
#define W_COLS 192        // C_OUT * 3 irreps
#define TILE_E 64         // edges per block (8 warps x 8 edges)
#define R_E    8          // edges per warp
#define THREADS 256

// smem layout (floats):
//  [0, 12288)                      W staged                       (48 KB)
//  [12288, 12288+8192)             inv dup f32x2: 64 e x 64 k     (32 KB)
//  [20480, 20480+4608)             stage: 8 warps x 576 floats    (18 KB)
#define SM_W    0
#define SM_INV  12288
#define SM_STG  (12288 + 8192)
#define SMEM_FLOATS (12288 + 8192 + 8*576)

typedef unsigned long long ull;

__device__ __forceinline__ void ffma2(ull& d, ull a, ull b) {
    asm("fma.rn.f32x2 %0, %1, %2, %0;" : "+l"(d) : "l"(a), "l"(b));
}

__global__ __launch_bounds__(THREADS, 2)
void sh_embed_kernel(const float* __restrict__ edge_vec,
                     const float* __restrict__ edge_inv,
                     const float* __restrict__ W_lin,
                     float* __restrict__ out,
                     int E) {
    extern __shared__ float smem[];
    float* Wsh = smem + SM_W;
    ull* inv2 = (ull*)(smem + SM_INV);
    float* stgAll = smem + SM_STG;

    const int tid  = threadIdx.x;
    const int wrp  = tid >> 5;
    const int cp   = tid & 31;          // channel pair id: channels 2cp, 2cp+1
    const int ebase = blockIdx.x * TILE_E;

    // ---- stage W [64][192] into smem (float4 coalesced) ----
    {
        const float4* src = (const float4*)W_lin;
        float4* dst = (float4*)Wsh;
        #pragma unroll
        for (int i = 0; i < 12; i++) {
            int idx = tid + i * THREADS;          // 12288/4 = 3072 float4
            dst[idx] = src[idx];
        }
    }

    // ---- stage invariants duplicated {v,v} : 64 rows x 64 cols ----
    {
        float2* inv2f = (float2*)inv2;   // [64][64] of float2
        #pragma unroll
        for (int i = 0; i < 4; i++) {
            int idx = tid + i * THREADS;          // 1024 float4 loads total
            int row = idx >> 4;                   // 16 float4 per row
            int c4  = idx & 15;
            int e   = ebase + row;
            float4 v = make_float4(0.f, 0.f, 0.f, 0.f);
            if (e < E) v = ((const float4*)edge_inv)[(size_t)e * 16 + c4];
            float4* p = (float4*)&inv2f[row * 64 + 4 * c4];
            p[0] = make_float4(v.x, v.x, v.y, v.y);
            p[1] = make_float4(v.z, v.z, v.w, v.w);
        }
    }
    __syncthreads();

    // ---- mainloop: 8 edges per warp, 2 channels per lane via f32x2,
    //      k unrolled x2 with LDS.128 broadcast invariants ----
    ull acc[R_E][3];
    #pragma unroll
    for (int r = 0; r < R_E; r++) {
        acc[r][0] = 0ull; acc[r][1] = 0ull; acc[r][2] = 0ull;
    }

    const ull* Ip = inv2 + (size_t)(wrp * R_E) * 64;
    const float* Wp = Wsh + 6 * cp;

    #pragma unroll 4
    for (int k = 0; k < 64; k += 2) {
        const float* wk = Wp + k * W_COLS;
        ull b0 = *(const ull*)(wk);
        ull b1 = *(const ull*)(wk + 2);
        ull b2 = *(const ull*)(wk + 4);
        ull c0 = *(const ull*)(wk + W_COLS);
        ull c1 = *(const ull*)(wk + W_COLS + 2);
        ull c2 = *(const ull*)(wk + W_COLS + 4);
        #pragma unroll
        for (int r = 0; r < R_E; r++) {
            ulonglong2 iv = *(const ulonglong2*)&Ip[r * 64 + k];  // {k, k+1} dups
            ffma2(acc[r][0], iv.x, b0);
            ffma2(acc[r][1], iv.x, b1);
            ffma2(acc[r][2], iv.x, b2);
            ffma2(acc[r][0], iv.y, c0);
            ffma2(acc[r][1], iv.y, c1);
            ffma2(acc[r][2], iv.y, c2);
        }
    }

    // ---- epilogue: SH weighting + coalesced store via smem staging ----
    const float SQ3   = 1.7320508075688772f;
    const float SQ5   = 2.2360679774997896f;
    const float SQ15  = 3.8729833462074170f;
    const float SQ15H = 1.9364916731037085f;

    float* stg = stgAll + wrp * 576;

    #pragma unroll
    for (int r = 0; r < R_E; r++) {
        int e = ebase + wrp * R_E + r;
        if (e >= E) break;   // uniform across warp

        // spherical harmonics (redundant per lane; cheap)
        const float* ev = edge_vec + (size_t)e * 3;
        float vx = ev[0], vy = ev[1], vz = ev[2];
        float rn = rsqrtf(vx * vx + vy * vy + vz * vz);
        float x = vx * rn, y = vy * rn, z = vz * rn;
        float sh1 = SQ3 * x, sh2 = SQ3 * y, sh3 = SQ3 * z;
        float sh4 = SQ15 * x * z;
        float sh5 = SQ15 * x * y;
        float sh6 = SQ5 * (y * y - 0.5f * (x * x + z * z));
        float sh7 = SQ15 * y * z;
        float sh8 = SQ15H * (z * z - x * x);

        // unpack accumulators: acc[r][j] lo/hi = gemm cols 6cp+2j, 6cp+2j+1
        float w00 = __uint_as_float((unsigned)(acc[r][0] & 0xffffffffull));
        float w01 = __uint_as_float((unsigned)(acc[r][0] >> 32));
        float w02 = __uint_as_float((unsigned)(acc[r][1] & 0xffffffffull));
        float w10 = __uint_as_float((unsigned)(acc[r][1] >> 32));
        float w11 = __uint_as_float((unsigned)(acc[r][2] & 0xffffffffull));
        float w12 = __uint_as_float((unsigned)(acc[r][2] >> 32));

        float val[18];
        val[0] = w00;
        val[1] = w01 * sh1;  val[2] = w01 * sh2;  val[3] = w01 * sh3;
        val[4] = w02 * sh4;  val[5] = w02 * sh5;  val[6] = w02 * sh6;
        val[7] = w02 * sh7;  val[8] = w02 * sh8;
        val[9] = w10;
        val[10] = w11 * sh1; val[11] = w11 * sh2; val[12] = w11 * sh3;
        val[13] = w12 * sh4; val[14] = w12 * sh5; val[15] = w12 * sh6;
        val[16] = w12 * sh7; val[17] = w12 * sh8;

        float2* stg2 = (float2*)(stg) + 9 * cp;
        #pragma unroll
        for (int j = 0; j < 9; j++)
            stg2[j] = make_float2(val[2 * j], val[2 * j + 1]);

        __syncwarp();

        // coalesced copy: 576 floats = 4 x (32 lanes x float4) + 1 x (32 x float2)
        float* dst = out + (size_t)e * 576;
        #pragma unroll
        for (int j = 0; j < 4; j++) {
            int idx = j * 128 + cp * 4;
            float4 v = *(const float4*)&stg[idx];
            *(float4*)&dst[idx] = v;
        }
        {
            int idx = 512 + cp * 2;
            float2 v = *(const float2*)&stg[idx];
            *(float2*)&dst[idx] = v;
        }
        __syncwarp();
    }
}

extern "C" void kernel_launch(void* const* d_in, const int* in_sizes, int n_in,
                              void* d_out, int out_size) {
    const float* edge_vec = (const float*)d_in[0];  // [E,3]
    const float* edge_inv = (const float*)d_in[1];  // [E,64]
    const float* W_lin    = (const float*)d_in[2];  // [64,192]
    float* out = (float*)d_out;                     // [E,64,9]

    int E = in_sizes[0] / 3;
    int blocks = (E + TILE_E - 1) / TILE_E;
    size_t smem = SMEM_FLOATS * sizeof(float);

    static bool attr_set = false;
    if (!attr_set) {
        cudaFuncSetAttribute(sh_embed_kernel,
                             cudaFuncAttributeMaxDynamicSharedMemorySize,
                             (int)smem);
        attr_set = true;
    }
    sh_embed_kernel<<<blocks, THREADS, smem>>>(edge_vec, edge_inv, W_lin, out, E);
}

// round 6
// speedup vs baseline: 1.5074x; 1.2284x over previous
#include <cuda_runtime.h>
#include <cstdint>

#define D_IN   64
#define C_OUT  64
#define W_COLS 192        // C_OUT * 3 irreps
#define TILE_E 64         // edges per block (8 warps x 8 edges)
#define R_E    8          // edges per warp
#define THREADS 256

// smem layout (floats):
//  [0, 12288)                  W staged                            (48 KB)
//  [12288, 12288+4096)         inv (undup): 64 e x 64 k            (16 KB)
//  [16384, 16384+9216)         stage: 8 warps x 2 slots x 576 f    (36 KB)
#define SM_W    0
#define SM_INV  12288
#define SM_STG  16384
#define SMEM_FLOATS (16384 + 9216)   // 25600 floats = 100 KB

typedef unsigned long long ull;

__device__ __forceinline__ void ffma2(ull& d, ull a, ull b) {
    asm("fma.rn.f32x2 %0, %1, %2, %0;" : "+l"(d) : "l"(a), "l"(b));
}
__device__ __forceinline__ ull dupf(float a) {
    ull r; asm("mov.b64 %0, {%1, %1};" : "=l"(r) : "f"(a)); return r;
}
__device__ __forceinline__ unsigned smem_u32(const void* p) {
    return (unsigned)__cvta_generic_to_shared(p);
}
__device__ __forceinline__ void bulk_store(void* gdst, unsigned ssrc, int bytes) {
    asm volatile("cp.async.bulk.global.shared::cta.bulk_group [%0], [%1], %2;"
                 :: "l"(gdst), "r"(ssrc), "r"(bytes) : "memory");
    asm volatile("cp.async.bulk.commit_group;" ::: "memory");
}
template <int N>
__device__ __forceinline__ void bulk_wait() {
    asm volatile("cp.async.bulk.wait_group.read %0;" :: "n"(N) : "memory");
}

__global__ __launch_bounds__(THREADS, 2)
void sh_embed_kernel(const float* __restrict__ edge_vec,
                     const float* __restrict__ edge_inv,
                     const float* __restrict__ W_lin,
                     float* __restrict__ out,
                     int E) {
    extern __shared__ float smem[];
    float* Wsh  = smem + SM_W;
    float* Inv  = smem + SM_INV;
    float* stgAll = smem + SM_STG;

    const int tid  = threadIdx.x;
    const int wrp  = tid >> 5;
    const int cp   = tid & 31;          // channel pair id: channels 2cp, 2cp+1
    const int ebase = blockIdx.x * TILE_E;

    // ---- stage W [64][192] into smem (float4 coalesced) ----
    {
        const float4* src = (const float4*)W_lin;
        float4* dst = (float4*)Wsh;
        #pragma unroll
        for (int i = 0; i < 12; i++) {
            int idx = tid + i * THREADS;          // 3072 float4
            dst[idx] = src[idx];
        }
    }

    // ---- stage invariants (no duplication): 64 rows x 64 cols ----
    {
        #pragma unroll
        for (int i = 0; i < 4; i++) {
            int idx = tid + i * THREADS;          // 1024 float4 loads total
            int row = idx >> 4;                   // 16 float4 per row
            int c4  = idx & 15;
            int e   = ebase + row;
            float4 v = make_float4(0.f, 0.f, 0.f, 0.f);
            if (e < E) v = ((const float4*)edge_inv)[(size_t)e * 16 + c4];
            ((float4*)Inv)[row * 16 + c4] = v;
        }
    }
    __syncthreads();

    // ---- mainloop: 8 edges/warp, 2 channels/lane via f32x2, k unrolled x2 ----
    ull acc[R_E][3];
    #pragma unroll
    for (int r = 0; r < R_E; r++) {
        acc[r][0] = 0ull; acc[r][1] = 0ull; acc[r][2] = 0ull;
    }

    const float* Ip = Inv + (size_t)(wrp * R_E) * 64;
    const float* Wp = Wsh + 6 * cp;

    #pragma unroll 4
    for (int k = 0; k < 64; k += 2) {
        const float* wk = Wp + k * W_COLS;
        ull b0 = *(const ull*)(wk);
        ull b1 = *(const ull*)(wk + 2);
        ull b2 = *(const ull*)(wk + 4);
        ull c0 = *(const ull*)(wk + W_COLS);
        ull c1 = *(const ull*)(wk + W_COLS + 2);
        ull c2 = *(const ull*)(wk + W_COLS + 4);
        #pragma unroll
        for (int r = 0; r < R_E; r++) {
            float2 iv = *(const float2*)&Ip[r * 64 + k];   // broadcast LDS.64
            ull ax = dupf(iv.x);
            ull ay = dupf(iv.y);
            ffma2(acc[r][0], ax, b0);
            ffma2(acc[r][1], ax, b1);
            ffma2(acc[r][2], ax, b2);
            ffma2(acc[r][0], ay, c0);
            ffma2(acc[r][1], ay, c1);
            ffma2(acc[r][2], ay, c2);
        }
    }

    // ---- epilogue: SH weighting, STS staging, TMA bulk store ----
    const float SQ3   = 1.7320508075688772f;
    const float SQ5   = 2.2360679774997896f;
    const float SQ15  = 3.8729833462074170f;
    const float SQ15H = 1.9364916731037085f;

    float* stg = stgAll + wrp * 1152;   // two 576-float slots per warp

    #pragma unroll
    for (int r = 0; r < R_E; r++) {
        int e = ebase + wrp * R_E + r;
        if (e >= E) break;   // uniform across warp

        float* slot = stg + (r & 1) * 576;

        // before reusing this slot, wait for the TMA issued 2 edges ago
        if (r >= 2 && cp == 0) bulk_wait<1>();
        __syncwarp();

        // spherical harmonics (redundant per lane; cheap)
        const float* ev = edge_vec + (size_t)e * 3;
        float vx = ev[0], vy = ev[1], vz = ev[2];
        float rn = rsqrtf(vx * vx + vy * vy + vz * vz);
        float x = vx * rn, y = vy * rn, z = vz * rn;
        float sh1 = SQ3 * x, sh2 = SQ3 * y, sh3 = SQ3 * z;
        float sh4 = SQ15 * x * z;
        float sh5 = SQ15 * x * y;
        float sh6 = SQ5 * (y * y - 0.5f * (x * x + z * z));
        float sh7 = SQ15 * y * z;
        float sh8 = SQ15H * (z * z - x * x);

        // unpack accumulators: acc[r][j] lo/hi = gemm cols 6cp+2j, 6cp+2j+1
        float w00 = __uint_as_float((unsigned)(acc[r][0] & 0xffffffffull));
        float w01 = __uint_as_float((unsigned)(acc[r][0] >> 32));
        float w02 = __uint_as_float((unsigned)(acc[r][1] & 0xffffffffull));
        float w10 = __uint_as_float((unsigned)(acc[r][1] >> 32));
        float w11 = __uint_as_float((unsigned)(acc[r][2] & 0xffffffffull));
        float w12 = __uint_as_float((unsigned)(acc[r][2] >> 32));

        float val[18];
        val[0] = w00;
        val[1] = w01 * sh1;  val[2] = w01 * sh2;  val[3] = w01 * sh3;
        val[4] = w02 * sh4;  val[5] = w02 * sh5;  val[6] = w02 * sh6;
        val[7] = w02 * sh7;  val[8] = w02 * sh8;
        val[9] = w10;
        val[10] = w11 * sh1; val[11] = w11 * sh2; val[12] = w11 * sh3;
        val[13] = w12 * sh4; val[14] = w12 * sh5; val[15] = w12 * sh6;
        val[16] = w12 * sh7; val[17] = w12 * sh8;

        // lane's 18 floats are contiguous at 72B stride (conflict-free phases)
        float2* stg2 = (float2*)slot + 9 * cp;
        #pragma unroll
        for (int j = 0; j < 9; j++)
            stg2[j] = make_float2(val[2 * j], val[2 * j + 1]);

        __syncwarp();

        if (cp == 0) {
            asm volatile("fence.proxy.async.shared::cta;" ::: "memory");
            bulk_store(out + (size_t)e * 576, smem_u32(slot), 576 * 4);
        }
    }

    // drain outstanding bulk stores before exit
    if (cp == 0) bulk_wait<0>();
}

extern "C" void kernel_launch(void* const* d_in, const int* in_sizes, int n_in,
                              void* d_out, int out_size) {
    const float* edge_vec = (const float*)d_in[0];  // [E,3]
    const float* edge_inv = (const float*)d_in[1];  // [E,64]
    const float* W_lin    = (const float*)d_in[2];  // [64,192]
    float* out = (float*)d_out;                     // [E,64,9]

    int E = in_sizes[0] / 3;
    int blocks = (E + TILE_E - 1) / TILE_E;
    size_t smem = SMEM_FLOATS * sizeof(float);

    static bool attr_set = false;
    if (!attr_set) {
        cudaFuncSetAttribute(sh_embed_kernel,
                             cudaFuncAttributeMaxDynamicSharedMemorySize,
                             (int)smem);
        attr_set = true;
    }
    sh_embed_kernel<<<blocks, THREADS, smem>>>(edge_vec, edge_inv, W_lin, out, E);
}